// round 12
// baseline (speedup 1.0000x reference)
#include <cuda_runtime.h>
#include <cuda_bf16.h>
#include <cstdint>

// PackedViterbi as a parallel matrix-product tree (transpose-free, fixed
// power-of-2 per-GEMM scaling, ping-pong tiles).
// R12: passA processes TWO independent GEMM chains per CTA (chunk c of
// sequences b=2by and b=2by+1, lengths sorted so trip counts match):
// one __syncthreads covers two GEMMs and each chain hides the other's
// latencies (within-warp ILP). 16 warps, R10 fragment layout (58-reg shape).
// passB/passC unchanged from R10 (binary-tree combine, measured fastest).

static constexpr int S   = 64;
static constexpr int TT  = 512;
static constexpr int BB  = 64;
static constexpr int LDA = 72;            // padded SMEM stride (bf16 elems)
static constexpr int TILE = S * LDA;      // bf16 elems per smem tile

__device__ __nv_bfloat16 g_buf1[64 * BB * S * S];
__device__ float         g_off1[64 * BB];
__device__ __nv_bfloat16 g_buf2[8 * BB * S * S];
__device__ float         g_off2[8 * BB];

__device__ __forceinline__ float ex2f_(float x) {
    float y; asm("ex2.approx.ftz.f32 %0, %1;" : "=f"(y) : "f"(x)); return y;
}
__device__ __forceinline__ void mma16816(float c[4], const uint32_t a[4],
                                         uint32_t b0, uint32_t b1) {
    asm volatile(
        "mma.sync.aligned.m16n8k16.row.col.f32.bf16.bf16.f32 "
        "{%0,%1,%2,%3}, {%4,%5,%6,%7}, {%8,%9}, {%0,%1,%2,%3};\n"
        : "+f"(c[0]), "+f"(c[1]), "+f"(c[2]), "+f"(c[3])
        : "r"(a[0]), "r"(a[1]), "r"(a[2]), "r"(a[3]), "r"(b0), "r"(b1));
}
__device__ __forceinline__ void ldm_x4_t(uint32_t a[4], uint32_t addr) {
    asm volatile("ldmatrix.sync.aligned.m8n8.x4.trans.shared.b16 {%0,%1,%2,%3}, [%4];"
                 : "=r"(a[0]), "=r"(a[1]), "=r"(a[2]), "=r"(a[3]) : "r"(addr));
}
__device__ __forceinline__ void ldm_x2_t(uint32_t b[2], uint32_t addr) {
    asm volatile("ldmatrix.sync.aligned.m8n8.x2.trans.shared.b16 {%0,%1}, [%2];"
                 : "=r"(b[0]), "=r"(b[1]) : "r"(addr));
}

struct F8 { float4 a, b; };
__device__ __forceinline__ F8 ldg8(const float* __restrict__ p) {
    F8 r; const float4* q = (const float4*)p; r.a = q[0]; r.b = q[1]; return r;
}
// 8 thetas -> E' = 2^(theta*log2e - 16), stored row-major (conflict-free)
__device__ __forceinline__ void conv_store(const F8& v, __nv_bfloat16* s) {
    const float L2E = 1.4426950408889634f;
    int idx = threadIdx.x * 8;
    float e[8];
    e[0] = ex2f_(fmaf(v.a.x, L2E, -16.f)); e[1] = ex2f_(fmaf(v.a.y, L2E, -16.f));
    e[2] = ex2f_(fmaf(v.a.z, L2E, -16.f)); e[3] = ex2f_(fmaf(v.a.w, L2E, -16.f));
    e[4] = ex2f_(fmaf(v.b.x, L2E, -16.f)); e[5] = ex2f_(fmaf(v.b.y, L2E, -16.f));
    e[6] = ex2f_(fmaf(v.b.z, L2E, -16.f)); e[7] = ex2f_(fmaf(v.b.w, L2E, -16.f));
    __nv_bfloat16 t[8];
#pragma unroll
    for (int q = 0; q < 8; ++q) t[q] = __float2bfloat16(e[q]);
    *(uint4*)(s + (idx >> 6) * LDA + (idx & 63)) = *(uint4*)t;
}
__device__ __forceinline__ void smem_put(const uint4& v, __nv_bfloat16* s) {
    int idx = threadIdx.x * 8;
    *(uint4*)(s + (idx >> 6) * LDA + (idx & 63)) = v;
}

// C = Asrc * op(Bsrc); no syncs inside. R10/R8 fragment layout (16 warps).
template <bool ATRANS, bool BLDM>
__device__ __forceinline__ void cta_compute(const __nv_bfloat16* Asm,
                                            const __nv_bfloat16* Btsm,
                                            float c[2][4]) {
    const int tid = threadIdx.x;
    const int w = tid >> 5, lane = tid & 31;
    const int g = lane >> 2, t4 = lane & 3;
    const int rb = (w >> 2) * 16;
    const int ng = (w & 3) * 2;

    uint32_t a[4][4];
    if (ATRANS) {
        const int mi = lane >> 3, r8 = lane & 7;
        const int colA = rb + ((mi & 1) ? 8 : 0);
        const int rowO = ((mi & 2) ? 8 : 0) + r8;
#pragma unroll
        for (int ks = 0; ks < 4; ++ks) {
            uint32_t ad = (uint32_t)__cvta_generic_to_shared(
                Asm + (ks * 16 + rowO) * LDA + colA);
            ldm_x4_t(a[ks], ad);
        }
    } else {
#pragma unroll
        for (int ks = 0; ks < 4; ++ks) {
            const __nv_bfloat16* base = Asm + (rb + g) * LDA + ks * 16 + t4 * 2;
            a[ks][0] = *(const uint32_t*)(base);
            a[ks][1] = *(const uint32_t*)(base + 8 * LDA);
            a[ks][2] = *(const uint32_t*)(base + 8);
            a[ks][3] = *(const uint32_t*)(base + 8 * LDA + 8);
        }
    }
#pragma unroll
    for (int nt = 0; nt < 2; ++nt) {
        c[nt][0] = c[nt][1] = c[nt][2] = c[nt][3] = 0.f;
        const int n0 = (ng + nt) * 8;
#pragma unroll
        for (int ks = 0; ks < 4; ++ks) {
            uint32_t b0, b1;
            if (BLDM) {
                const int r8 = lane & 7, ti = (lane >> 3) & 1;
                uint32_t ad = (uint32_t)__cvta_generic_to_shared(
                    Btsm + (ks * 16 + ti * 8 + r8) * LDA + n0);
                uint32_t bb[2]; ldm_x2_t(bb, ad);
                b0 = bb[0]; b1 = bb[1];
            } else {
                const __nv_bfloat16* bb = Btsm + (n0 + g) * LDA + ks * 16 + t4 * 2;
                b0 = *(const uint32_t*)bb;
                b1 = *(const uint32_t*)(bb + 8);
            }
            mma16816(c[nt], a[ks], b0, b1);
        }
    }
}

__device__ __forceinline__ void wb_smem(const float c[2][4], float scl,
                                        __nv_bfloat16* dst) {
    const int tid = threadIdx.x;
    const int w = tid >> 5, lane = tid & 31;
    const int g = lane >> 2, t4 = lane & 3;
    const int rb = (w >> 2) * 16;
    const int ng = (w & 3) * 2;
#pragma unroll
    for (int nt = 0; nt < 2; ++nt) {
        int col = (ng + nt) * 8 + t4 * 2;
        __nv_bfloat162 lo = __floats2bfloat162_rn(c[nt][0] * scl, c[nt][1] * scl);
        __nv_bfloat162 hi = __floats2bfloat162_rn(c[nt][2] * scl, c[nt][3] * scl);
        *(uint32_t*)(dst + (rb + g) * LDA + col)     = *(uint32_t*)&lo;
        *(uint32_t*)(dst + (rb + g + 8) * LDA + col) = *(uint32_t*)&hi;
    }
}
__device__ __forceinline__ void wb_global(const float c[2][4], float scl,
                                          __nv_bfloat16* __restrict__ dst) {
    const int tid = threadIdx.x;
    const int w = tid >> 5, lane = tid & 31;
    const int g = lane >> 2, t4 = lane & 3;
    const int rb = (w >> 2) * 16;
    const int ng = (w & 3) * 2;
#pragma unroll
    for (int nt = 0; nt < 2; ++nt) {
        int col = (ng + nt) * 8 + t4 * 2;
        __nv_bfloat162 lo = __floats2bfloat162_rn(c[nt][0] * scl, c[nt][1] * scl);
        __nv_bfloat162 hi = __floats2bfloat162_rn(c[nt][2] * scl, c[nt][3] * scl);
        *(uint32_t*)(dst + (rb + g) * S + col)     = *(uint32_t*)&lo;
        *(uint32_t*)(dst + (rb + g + 8) * S + col) = *(uint32_t*)&hi;
    }
}

// exact power-of-2 scale from final C regs: scale = 2^-sft, max*scale in [0.5,1)
__device__ __forceinline__ void exact_scale(const float c[2][4], float* red,
                                            float& scale, float& sft) {
    const int tid = threadIdx.x;
    const int w = tid >> 5, lane = tid & 31;
    float m = 0.f;
#pragma unroll
    for (int nt = 0; nt < 2; ++nt)
#pragma unroll
        for (int q = 0; q < 4; ++q) m = fmaxf(m, c[nt][q]);
#pragma unroll
    for (int o = 16; o; o >>= 1)
        m = fmaxf(m, __shfl_xor_sync(0xffffffffu, m, o));
    if (lane == 0) red[w] = m;
    __syncthreads();
    if (tid == 0) {
        float mm = red[0];
#pragma unroll
        for (int i = 1; i < 16; ++i) mm = fmaxf(mm, red[i]);
        int s = (int)((__float_as_uint(mm) >> 23) & 0xFF) - 126;
        red[16] = __uint_as_float((uint32_t)(127 - s) << 23);
        red[17] = (float)s;
    }
    __syncthreads();
    scale = red[16];
    sft   = red[17];
}

// ---- Pass A: two chains per CTA (chunk c of b=2by and b=2by+1) ----------------
__global__ void __launch_bounds__(512, 1)
passA(const float* __restrict__ theta, const int* __restrict__ lengths) {
    extern __shared__ __nv_bfloat16 dynA[];
    __nv_bfloat16* A0 = dynA;                 // [2][TILE]
    __nv_bfloat16* B0 = dynA + 2 * TILE;      // [2][TILE]
    __nv_bfloat16* A1 = dynA + 4 * TILE;
    __nv_bfloat16* B1 = dynA + 6 * TILE;
    float* red0 = (float*)(dynA + 8 * TILE);
    float* red1 = red0 + 20;

    const int c  = blockIdx.x;
    const int b0 = blockIdx.y * 2, b1 = b0 + 1;
    const int L0 = lengths[b0],    L1 = lengths[b1];
    const int t0 = c * 8;
    const bool act0 = L0 > t0, act1 = L1 > t0;
    if (!act0 && !act1) return;

    const int thi0 = min(L0, t0 + 8), thi1 = min(L1, t0 + 8);
    const int ng0 = act0 ? (thi0 - t0 - 1) : -1;   // #GEMMs in chain
    const int ng1 = act1 ? (thi1 - t0 - 1) : -1;
    const int kmax = max(ng0, ng1);

    const int idx = threadIdx.x * 8;
    const size_t mat = (size_t)S * S;
    const size_t tstride = (size_t)BB * mat;
    const float* tb0 = theta + (size_t)b0 * mat + idx;
    const float* tb1 = theta + (size_t)b1 * mat + idx;

    F8 rN0, rN1;
    // prologue: leaf t0 into A[0], leaf t0+1 into B[0], prefetch t0+2
    if (act0) { F8 rA = ldg8(tb0 + (size_t)t0 * tstride); conv_store(rA, A0); }
    if (act1) { F8 rA = ldg8(tb1 + (size_t)t0 * tstride); conv_store(rA, A1); }
    if (ng0 > 0) {
        rN0 = ldg8(tb0 + (size_t)(t0 + 1) * tstride); conv_store(rN0, B0);
        if (t0 + 2 < thi0) rN0 = ldg8(tb0 + (size_t)(t0 + 2) * tstride);
    }
    if (ng1 > 0) {
        rN1 = ldg8(tb1 + (size_t)(t0 + 1) * tstride); conv_store(rN1, B1);
        if (t0 + 2 < thi1) rN1 = ldg8(tb1 + (size_t)(t0 + 2) * tstride);
    }
    __syncthreads();

    // single-leaf chains: write transposed copy now
    const int r = idx >> 6, c0c = idx & 63;
    if (act0 && ng0 == 0) {
        __nv_bfloat16 t[8];
#pragma unroll
        for (int q = 0; q < 8; ++q) t[q] = A0[(c0c + q) * LDA + r];
        *(uint4*)(g_buf1 + ((size_t)c * BB + b0) * mat + idx) = *(uint4*)t;
        if (threadIdx.x == 0) g_off1[c * BB + b0] = 16.f;
    }
    if (act1 && ng1 == 0) {
        __nv_bfloat16 t[8];
#pragma unroll
        for (int q = 0; q < 8; ++q) t[q] = A1[(c0c + q) * LDA + r];
        *(uint4*)(g_buf1 + ((size_t)c * BB + b1) * mat + idx) = *(uint4*)t;
        if (threadIdx.x == 0) g_off1[c * BB + b1] = 16.f;
    }
    if (kmax <= 0) return;

    float c0_[2][4], c1_[2][4];
    if (ng0 > 0) cta_compute<true, false>(A0, B0, c0_);   // GEMM 0 (A = E^T)
    if (ng1 > 0) cta_compute<true, false>(A1, B1, c1_);

    int pa = 0, pb = 0;
    for (int k = 1; k < kmax; ++k) {
        if (k < ng0) {
            conv_store(rN0, B0 + (pb ^ 1) * TILE);
            if (t0 + k + 2 < thi0) rN0 = ldg8(tb0 + (size_t)(t0 + k + 2) * tstride);
            wb_smem(c0_, 512.f, A0 + (pa ^ 1) * TILE);
        }
        if (k < ng1) {
            conv_store(rN1, B1 + (pb ^ 1) * TILE);
            if (t0 + k + 2 < thi1) rN1 = ldg8(tb1 + (size_t)(t0 + k + 2) * tstride);
            wb_smem(c1_, 512.f, A1 + (pa ^ 1) * TILE);
        }
        pa ^= 1; pb ^= 1;
        __syncthreads();
        if (k < ng0) cta_compute<false, false>(A0 + pa * TILE, B0 + pb * TILE, c0_);
        if (k < ng1) cta_compute<false, false>(A1 + pa * TILE, B1 + pb * TILE, c1_);
    }

    if (ng0 > 0) {
        float scale, sft;
        exact_scale(c0_, red0, scale, sft);
        wb_global(c0_, scale, g_buf1 + ((size_t)c * BB + b0) * mat);
        if (threadIdx.x == 0)
            g_off1[c * BB + b0] = 16.f * (float)(thi0 - t0) - 9.f * (float)(ng0 - 1) + sft;
    }
    if (ng1 > 0) {
        float scale, sft;
        exact_scale(c1_, red1, scale, sft);
        wb_global(c1_, scale, g_buf1 + ((size_t)c * BB + b1) * mat);
        if (threadIdx.x == 0)
            g_off1[c * BB + b1] = 16.f * (float)(thi1 - t0) - 9.f * (float)(ng1 - 1) + sft;
    }
}

// ---- binary-tree combine of n (2..8) tiles in smem, ascending order ----------
__device__ __forceinline__ int tree_combine(__nv_bfloat16* tiles, int n,
                                            float cF[2][4]) {
    int ngm = 0;
    float c1[2][4];
    const float FS = 0.0625f;
#define TP(i) (tiles + (i) * TILE)
    cta_compute<false, true>(TP(0), TP(1), cF);
    if (n == 2) return 0;
    if (n > 3) cta_compute<false, true>(TP(2), TP(3), c1);
    __syncthreads();
    wb_smem(cF, FS, TP(0)); ++ngm;
    if (n > 3) { wb_smem(c1, FS, TP(2)); ++ngm; }
    __syncthreads();
    if (n > 5) {
        cta_compute<false, true>(TP(4), TP(5), cF);
        if (n > 7) cta_compute<false, true>(TP(6), TP(7), c1);
        __syncthreads();
        wb_smem(cF, FS, TP(4)); ++ngm;
        if (n > 7) { wb_smem(c1, FS, TP(6)); ++ngm; }
        __syncthreads();
    }
    if (n <= 4) {
        cta_compute<false, true>(TP(0), TP(2), cF);   // final
        return ngm;
    }
    cta_compute<false, true>(TP(0), TP(2), cF);
    if (n > 6) cta_compute<false, true>(TP(4), TP(6), c1);
    __syncthreads();
    wb_smem(cF, FS, TP(0)); ++ngm;
    if (n > 6) { wb_smem(c1, FS, TP(4)); ++ngm; }
    __syncthreads();
    cta_compute<false, true>(TP(0), TP(4), cF);       // final
    return ngm;
#undef TP
}

// ---- Pass B -------------------------------------------------------------------
__global__ void __launch_bounds__(512, 2)
passB(const int* __restrict__ lengths) {
    extern __shared__ __nv_bfloat16 dyn[];
    __nv_bfloat16* tiles = dyn;
    float* red = (float*)(dyn + 8 * TILE);
    const int cc = blockIdx.x, b = blockIdx.y;
    const int L = lengths[b];
    const int totalChunks = (L + 7) >> 3;
    const int nch = min(totalChunks - cc * 8, 8);
    if (nch <= 0) return;
    const int cb = cc * 8;
    const int idx = threadIdx.x * 8;
    const size_t mat = (size_t)S * S;

    if (nch == 1) {
        *(uint4*)(g_buf2 + ((size_t)cc * BB + b) * mat + idx) =
            *(const uint4*)(g_buf1 + ((size_t)cb * BB + b) * mat + idx);
        if (threadIdx.x == 0) g_off2[cc * BB + b] = g_off1[cb * BB + b];
        return;
    }

    float offsum = 0.f;
    for (int k = 0; k < nch; ++k) {
        smem_put(*(const uint4*)(g_buf1 + ((size_t)(cb + k) * BB + b) * mat + idx),
                 tiles + k * TILE);
        offsum += g_off1[(cb + k) * BB + b];
    }
    __syncthreads();

    float cF[2][4];
    int ngm = tree_combine(tiles, nch, cF);

    float scale, sft;
    exact_scale(cF, red, scale, sft);
    wb_global(cF, scale, g_buf2 + ((size_t)cc * BB + b) * mat);
    if (threadIdx.x == 0)
        g_off2[cc * BB + b] = offsum + 4.f * (float)ngm + sft;
}

// ---- Pass C -------------------------------------------------------------------
__global__ void __launch_bounds__(512, 1)
passC(const int* __restrict__ lengths, float* __restrict__ out) {
    extern __shared__ __nv_bfloat16 dyn[];
    __nv_bfloat16* tiles = dyn;
    float* red = (float*)(dyn + 8 * TILE);
    const int b = blockIdx.x;
    const int L = lengths[b];
    const int totalChunks = (L + 7) >> 3;
    const int n = (totalChunks + 7) >> 3;
    const int idx = threadIdx.x * 8;
    const int w = threadIdx.x >> 5, lane = threadIdx.x & 31;
    const size_t mat = (size_t)S * S;

    float s, off;
    if (n == 1) {
        uint4 v = *(const uint4*)(g_buf2 + (size_t)b * mat + idx);
        const __nv_bfloat16* h = (const __nv_bfloat16*)&v;
        s = 0.f;
#pragma unroll
        for (int q = 0; q < 8; ++q) s += __bfloat162float(h[q]);
        off = g_off2[b];
    } else {
        float offsum = 0.f;
        for (int k = 0; k < n; ++k) {
            smem_put(*(const uint4*)(g_buf2 + ((size_t)k * BB + b) * mat + idx),
                     tiles + k * TILE);
            offsum += g_off2[k * BB + b];
        }
        __syncthreads();
        float cF[2][4];
        int ngm = tree_combine(tiles, n, cF);
        off = offsum + 4.f * (float)ngm;
        s = 0.f;
#pragma unroll
        for (int nt = 0; nt < 2; ++nt)
#pragma unroll
            for (int q = 0; q < 4; ++q) s += cF[nt][q];
    }

#pragma unroll
    for (int o = 16; o; o >>= 1) s += __shfl_xor_sync(0xffffffffu, s, o);
    if (lane == 0) red[w] = s;
    __syncthreads();
    if (threadIdx.x == 0) {
        float tot = red[0];
#pragma unroll
        for (int i = 1; i < 16; ++i) tot += red[i];
        double vt = ((double)log2f(tot) + (double)off) * 0.6931471805599453094;
        out[b] = (float)vt;
    }
}

extern "C" void kernel_launch(void* const* d_in, const int* in_sizes, int n_in,
                              void* d_out, int out_size)
{
    const float* theta   = (const float*)d_in[0];
    const int*   lengths = (const int*)d_in[1];
    float*       out     = (float*)d_out;

    const int DYN  = 8 * TILE * (int)sizeof(__nv_bfloat16) + 32 * (int)sizeof(float);
    const int DYNA = 8 * TILE * (int)sizeof(__nv_bfloat16) + 48 * (int)sizeof(float);
    static int configured = -1;
    if (configured < 0) {
        cudaFuncSetAttribute(passA, cudaFuncAttributeMaxDynamicSharedMemorySize, DYNA);
        cudaFuncSetAttribute(passB, cudaFuncAttributeMaxDynamicSharedMemorySize, DYN);
        cudaFuncSetAttribute(passC, cudaFuncAttributeMaxDynamicSharedMemorySize, DYN);
        configured = 1;
    }

    passA<<<dim3(TT / 8, BB / 2), 512, DYNA>>>(theta, lengths);
    passB<<<dim3(TT / 64, BB), 512, DYN>>>(lengths);
    passC<<<BB, 512, DYN>>>(lengths, out);
}

// round 13
// speedup vs baseline: 1.0878x; 1.0878x over previous
#include <cuda_runtime.h>
#include <cuda_bf16.h>
#include <cstdint>

// PackedViterbi as a parallel matrix-product tree.
// R13 passA: REGISTER-RESIDENT running product. Each of 4 warps owns a 16x64
// C slab (c[8][4]). Key identity: mma m16n8k16's C-fragment layout == A-fragment
// layout under n->k renaming, so the next GEMM's A operand is packed from the
// previous C registers (32 FMUL + 16 CVT) -- A never round-trips through SMEM.
// Per-GEMM SMEM traffic drops 76KB -> 40KB (the measured crossbar wall).
// 128-thread CTAs, 3 rotating leaf buffers, conv(leaf j+2) overlapped with GEMM j,
// 6 CTAs/SM. passB/passC = R10's proven 512-thread binary-tree combine.

static constexpr int S   = 64;
static constexpr int TT  = 512;
static constexpr int BB  = 64;
static constexpr int LDA = 72;            // padded SMEM stride (bf16 elems)
static constexpr int TILE = S * LDA;      // bf16 elems per smem tile

__device__ __nv_bfloat16 g_buf1[64 * BB * S * S];
__device__ float         g_off1[64 * BB];
__device__ __nv_bfloat16 g_buf2[8 * BB * S * S];
__device__ float         g_off2[8 * BB];

__device__ __forceinline__ float ex2f_(float x) {
    float y; asm("ex2.approx.ftz.f32 %0, %1;" : "=f"(y) : "f"(x)); return y;
}
__device__ __forceinline__ void mma16816(float c[4], const uint32_t a[4],
                                         uint32_t b0, uint32_t b1) {
    asm volatile(
        "mma.sync.aligned.m16n8k16.row.col.f32.bf16.bf16.f32 "
        "{%0,%1,%2,%3}, {%4,%5,%6,%7}, {%8,%9}, {%0,%1,%2,%3};\n"
        : "+f"(c[0]), "+f"(c[1]), "+f"(c[2]), "+f"(c[3])
        : "r"(a[0]), "r"(a[1]), "r"(a[2]), "r"(a[3]), "r"(b0), "r"(b1));
}
__device__ __forceinline__ void ldm_x4_t(uint32_t a[4], uint32_t addr) {
    asm volatile("ldmatrix.sync.aligned.m8n8.x4.trans.shared.b16 {%0,%1,%2,%3}, [%4];"
                 : "=r"(a[0]), "=r"(a[1]), "=r"(a[2]), "=r"(a[3]) : "r"(addr));
}
__device__ __forceinline__ void ldm_x2_t(uint32_t b[2], uint32_t addr) {
    asm volatile("ldmatrix.sync.aligned.m8n8.x2.trans.shared.b16 {%0,%1}, [%2];"
                 : "=r"(b[0]), "=r"(b[1]) : "r"(addr));
}
__device__ __forceinline__ uint32_t bf2u(__nv_bfloat162 v) {
    return *reinterpret_cast<uint32_t*>(&v);
}

// ===================== passA helpers (128 threads, 4 warps) ====================

// convert one 64x64 theta leaf -> E' = 2^(x*log2e - 16) into smem (row-major).
// thread covers row r = tid>>1, cols (tid&1)*32 .. +31.
__device__ __forceinline__ void conv_store128(const float* __restrict__ g,
                                              __nv_bfloat16* s) {
    const float L2E = 1.4426950408889634f;
    const int r  = threadIdx.x >> 1;
    const int c0 = (threadIdx.x & 1) * 32;
    const float* src = g + r * S + c0;
    __nv_bfloat16* dst = s + r * LDA + c0;
#pragma unroll
    for (int h = 0; h < 4; ++h) {
        float4 v0 = *(const float4*)(src + h * 8);
        float4 v1 = *(const float4*)(src + h * 8 + 4);
        __nv_bfloat16 t[8];
        t[0] = __float2bfloat16(ex2f_(fmaf(v0.x, L2E, -16.f)));
        t[1] = __float2bfloat16(ex2f_(fmaf(v0.y, L2E, -16.f)));
        t[2] = __float2bfloat16(ex2f_(fmaf(v0.z, L2E, -16.f)));
        t[3] = __float2bfloat16(ex2f_(fmaf(v0.w, L2E, -16.f)));
        t[4] = __float2bfloat16(ex2f_(fmaf(v1.x, L2E, -16.f)));
        t[5] = __float2bfloat16(ex2f_(fmaf(v1.y, L2E, -16.f)));
        t[6] = __float2bfloat16(ex2f_(fmaf(v1.z, L2E, -16.f)));
        t[7] = __float2bfloat16(ex2f_(fmaf(v1.w, L2E, -16.f)));
        *(uint4*)(dst + h * 8) = *(uint4*)t;
    }
}

// c[8][4] += apack(16x64 A slab) * B(64x64 from smem), C zeroed inside.
__device__ __forceinline__ void mma_chain(const uint32_t apack[16],
                                          const __nv_bfloat16* Bsm,
                                          float c[8][4]) {
    const int lane = threadIdx.x & 31;
    const int g = lane >> 2, t4 = lane & 3;
#pragma unroll
    for (int nt = 0; nt < 8; ++nt) {
        c[nt][0] = c[nt][1] = c[nt][2] = c[nt][3] = 0.f;
        const __nv_bfloat16* bb = Bsm + (nt * 8 + g) * LDA + t4 * 2;
#pragma unroll
        for (int ks = 0; ks < 4; ++ks) {
            uint32_t b0 = *(const uint32_t*)(bb + ks * 16);
            uint32_t b1 = *(const uint32_t*)(bb + ks * 16 + 8);
            mma16816(c[nt], apack + ks * 4, b0, b1);
        }
    }
}

// A-fragments for the NEXT GEMM from current C regs (scaled): layout identity.
__device__ __forceinline__ void packA(const float c[8][4], uint32_t apack[16],
                                      float scl) {
#pragma unroll
    for (int ks = 0; ks < 4; ++ks) {
        apack[ks*4+0] = bf2u(__floats2bfloat162_rn(c[2*ks][0]*scl,   c[2*ks][1]*scl));
        apack[ks*4+1] = bf2u(__floats2bfloat162_rn(c[2*ks][2]*scl,   c[2*ks][3]*scl));
        apack[ks*4+2] = bf2u(__floats2bfloat162_rn(c[2*ks+1][0]*scl, c[2*ks+1][1]*scl));
        apack[ks*4+3] = bf2u(__floats2bfloat162_rn(c[2*ks+1][2]*scl, c[2*ks+1][3]*scl));
    }
}

// exact power-of-2 scale over 4 warps
__device__ __forceinline__ void exact_scale4(const float c[8][4], float* red,
                                             float& scale, float& sft) {
    const int tid = threadIdx.x;
    const int w = tid >> 5, lane = tid & 31;
    float m = 0.f;
#pragma unroll
    for (int nt = 0; nt < 8; ++nt)
#pragma unroll
        for (int q = 0; q < 4; ++q) m = fmaxf(m, c[nt][q]);
#pragma unroll
    for (int o = 16; o; o >>= 1)
        m = fmaxf(m, __shfl_xor_sync(0xffffffffu, m, o));
    if (lane == 0) red[w] = m;
    __syncthreads();
    if (tid == 0) {
        float mm = fmaxf(fmaxf(red[0], red[1]), fmaxf(red[2], red[3]));
        int s = (int)((__float_as_uint(mm) >> 23) & 0xFF) - 126;
        red[4] = __uint_as_float((uint32_t)(127 - s) << 23);
        red[5] = (float)s;
    }
    __syncthreads();
    scale = red[4];
    sft   = red[5];
}

__device__ __forceinline__ void wb_global4(const float c[8][4], float scl,
                                           __nv_bfloat16* __restrict__ dst) {
    const int tid = threadIdx.x;
    const int w = tid >> 5, lane = tid & 31;
    const int g = lane >> 2, t4 = lane & 3;
    const int rb = w * 16;
#pragma unroll
    for (int nt = 0; nt < 8; ++nt) {
        int col = nt * 8 + t4 * 2;
        __nv_bfloat162 lo = __floats2bfloat162_rn(c[nt][0] * scl, c[nt][1] * scl);
        __nv_bfloat162 hi = __floats2bfloat162_rn(c[nt][2] * scl, c[nt][3] * scl);
        *(uint32_t*)(dst + (rb + g) * S + col)     = bf2u(lo);
        *(uint32_t*)(dst + (rb + g + 8) * S + col) = bf2u(hi);
    }
}

// ---- Pass A -------------------------------------------------------------------
__global__ void __launch_bounds__(128, 6)
passA(const float* __restrict__ theta, const int* __restrict__ lengths) {
    __shared__ __nv_bfloat16 B3[3][TILE];
    __shared__ float red[8];
    const int c = blockIdx.x, b = blockIdx.y;
    const int L = lengths[b];
    const int t0 = c * 8;
    if (L <= t0) return;
    const int thi = min(L, t0 + 8);
    const int ngemm = thi - t0 - 1;
    const size_t mat = (size_t)S * S;
    const float* base = theta + (size_t)b * mat;
    const size_t tstride = (size_t)BB * mat;

    conv_store128(base + (size_t)t0 * tstride, B3[0]);
    if (ngemm > 0) conv_store128(base + (size_t)(t0 + 1) * tstride, B3[1]);
    __syncthreads();

    if (ngemm == 0) {                      // single leaf: store E^T
        const int r = threadIdx.x >> 1, c0 = (threadIdx.x & 1) * 32;
        __nv_bfloat16* dst = g_buf1 + ((size_t)c * BB + b) * mat + r * S + c0;
#pragma unroll
        for (int h = 0; h < 4; ++h) {
            __nv_bfloat16 t[8];
#pragma unroll
            for (int q = 0; q < 8; ++q) t[q] = B3[0][(c0 + h * 8 + q) * LDA + r];
            *(uint4*)(dst + h * 8) = *(uint4*)t;
        }
        if (threadIdx.x == 0) g_off1[c * BB + b] = 16.f;
        return;
    }

    const int w = threadIdx.x >> 5, lane = threadIdx.x & 31;
    const int rb = w * 16;

    uint32_t apack[16];
    {   // A = E_{t0}^T via ldmatrix.trans on the direct tile
        const int mi = lane >> 3, r8 = lane & 7;
        const int colA = rb + ((mi & 1) ? 8 : 0);
        const int rowO = ((mi & 2) ? 8 : 0) + r8;
#pragma unroll
        for (int ks = 0; ks < 4; ++ks) {
            uint32_t ad = (uint32_t)__cvta_generic_to_shared(
                B3[0] + (ks * 16 + rowO) * LDA + colA);
            ldm_x4_t(apack + ks * 4, ad);
        }
    }
    if (ngemm > 1) conv_store128(base + (size_t)(t0 + 2) * tstride, B3[2]);

    float c_[8][4];
    mma_chain(apack, B3[1], c_);           // GEMM 0
    __syncthreads();

    for (int j = 1; j < ngemm; ++j) {
        packA(c_, apack, 512.f);           // fixed x2^9, from registers
        if (j + 1 < ngemm)
            conv_store128(base + (size_t)(t0 + j + 2) * tstride, B3[(j + 2) % 3]);
        mma_chain(apack, B3[(j + 1) % 3], c_);
        __syncthreads();
    }

    float scale, sft;
    exact_scale4(c_, red, scale, sft);
    wb_global4(c_, scale, g_buf1 + ((size_t)c * BB + b) * mat);
    if (threadIdx.x == 0)
        g_off1[c * BB + b] = 16.f * (float)(thi - t0) - 9.f * (float)(ngemm - 1) + sft;
}

// ===================== passB / passC (R10, 512 threads) ========================

__device__ __forceinline__ void smem_put(const uint4& v, __nv_bfloat16* s) {
    int idx = threadIdx.x * 8;
    *(uint4*)(s + (idx >> 6) * LDA + (idx & 63)) = v;
}

template <bool BLDM>
__device__ __forceinline__ void cta_compute16(const __nv_bfloat16* Asm,
                                              const __nv_bfloat16* Btsm,
                                              float c[2][4]) {
    const int tid = threadIdx.x;
    const int w = tid >> 5, lane = tid & 31;
    const int g = lane >> 2, t4 = lane & 3;
    const int rb = (w >> 2) * 16;
    const int ng = (w & 3) * 2;

    uint32_t a[4][4];
#pragma unroll
    for (int ks = 0; ks < 4; ++ks) {
        const __nv_bfloat16* baseA = Asm + (rb + g) * LDA + ks * 16 + t4 * 2;
        a[ks][0] = *(const uint32_t*)(baseA);
        a[ks][1] = *(const uint32_t*)(baseA + 8 * LDA);
        a[ks][2] = *(const uint32_t*)(baseA + 8);
        a[ks][3] = *(const uint32_t*)(baseA + 8 * LDA + 8);
    }
#pragma unroll
    for (int nt = 0; nt < 2; ++nt) {
        c[nt][0] = c[nt][1] = c[nt][2] = c[nt][3] = 0.f;
        const int n0 = (ng + nt) * 8;
#pragma unroll
        for (int ks = 0; ks < 4; ++ks) {
            uint32_t b0, b1;
            if (BLDM) {
                const int r8 = lane & 7, ti = (lane >> 3) & 1;
                uint32_t ad = (uint32_t)__cvta_generic_to_shared(
                    Btsm + (ks * 16 + ti * 8 + r8) * LDA + n0);
                uint32_t bb[2]; ldm_x2_t(bb, ad);
                b0 = bb[0]; b1 = bb[1];
            } else {
                const __nv_bfloat16* bb = Btsm + (n0 + g) * LDA + ks * 16 + t4 * 2;
                b0 = *(const uint32_t*)bb;
                b1 = *(const uint32_t*)(bb + 8);
            }
            mma16816(c[nt], a[ks], b0, b1);
        }
    }
}

__device__ __forceinline__ void wb_smem16(const float c[2][4], float scl,
                                          __nv_bfloat16* dst) {
    const int tid = threadIdx.x;
    const int w = tid >> 5, lane = tid & 31;
    const int g = lane >> 2, t4 = lane & 3;
    const int rb = (w >> 2) * 16;
    const int ng = (w & 3) * 2;
#pragma unroll
    for (int nt = 0; nt < 2; ++nt) {
        int col = (ng + nt) * 8 + t4 * 2;
        __nv_bfloat162 lo = __floats2bfloat162_rn(c[nt][0] * scl, c[nt][1] * scl);
        __nv_bfloat162 hi = __floats2bfloat162_rn(c[nt][2] * scl, c[nt][3] * scl);
        *(uint32_t*)(dst + (rb + g) * LDA + col)     = bf2u(lo);
        *(uint32_t*)(dst + (rb + g + 8) * LDA + col) = bf2u(hi);
    }
}
__device__ __forceinline__ void wb_global16(const float c[2][4], float scl,
                                            __nv_bfloat16* __restrict__ dst) {
    const int tid = threadIdx.x;
    const int w = tid >> 5, lane = tid & 31;
    const int g = lane >> 2, t4 = lane & 3;
    const int rb = (w >> 2) * 16;
    const int ng = (w & 3) * 2;
#pragma unroll
    for (int nt = 0; nt < 2; ++nt) {
        int col = (ng + nt) * 8 + t4 * 2;
        __nv_bfloat162 lo = __floats2bfloat162_rn(c[nt][0] * scl, c[nt][1] * scl);
        __nv_bfloat162 hi = __floats2bfloat162_rn(c[nt][2] * scl, c[nt][3] * scl);
        *(uint32_t*)(dst + (rb + g) * S + col)     = bf2u(lo);
        *(uint32_t*)(dst + (rb + g + 8) * S + col) = bf2u(hi);
    }
}
__device__ __forceinline__ void exact_scale16(const float c[2][4], float* red,
                                              float& scale, float& sft) {
    const int tid = threadIdx.x;
    const int w = tid >> 5, lane = tid & 31;
    float m = 0.f;
#pragma unroll
    for (int nt = 0; nt < 2; ++nt)
#pragma unroll
        for (int q = 0; q < 4; ++q) m = fmaxf(m, c[nt][q]);
#pragma unroll
    for (int o = 16; o; o >>= 1)
        m = fmaxf(m, __shfl_xor_sync(0xffffffffu, m, o));
    if (lane == 0) red[w] = m;
    __syncthreads();
    if (tid == 0) {
        float mm = red[0];
#pragma unroll
        for (int i = 1; i < 16; ++i) mm = fmaxf(mm, red[i]);
        int s = (int)((__float_as_uint(mm) >> 23) & 0xFF) - 126;
        red[16] = __uint_as_float((uint32_t)(127 - s) << 23);
        red[17] = (float)s;
    }
    __syncthreads();
    scale = red[16];
    sft   = red[17];
}

__device__ __forceinline__ int tree_combine(__nv_bfloat16* tiles, int n,
                                            float cF[2][4]) {
    int ngm = 0;
    float c1[2][4];
    const float FS = 0.0625f;
#define TP(i) (tiles + (i) * TILE)
    cta_compute16<true>(TP(0), TP(1), cF);
    if (n == 2) return 0;
    if (n > 3) cta_compute16<true>(TP(2), TP(3), c1);
    __syncthreads();
    wb_smem16(cF, FS, TP(0)); ++ngm;
    if (n > 3) { wb_smem16(c1, FS, TP(2)); ++ngm; }
    __syncthreads();
    if (n > 5) {
        cta_compute16<true>(TP(4), TP(5), cF);
        if (n > 7) cta_compute16<true>(TP(6), TP(7), c1);
        __syncthreads();
        wb_smem16(cF, FS, TP(4)); ++ngm;
        if (n > 7) { wb_smem16(c1, FS, TP(6)); ++ngm; }
        __syncthreads();
    }
    if (n <= 4) {
        cta_compute16<true>(TP(0), TP(2), cF);
        return ngm;
    }
    cta_compute16<true>(TP(0), TP(2), cF);
    if (n > 6) cta_compute16<true>(TP(4), TP(6), c1);
    __syncthreads();
    wb_smem16(cF, FS, TP(0)); ++ngm;
    if (n > 6) { wb_smem16(c1, FS, TP(4)); ++ngm; }
    __syncthreads();
    cta_compute16<true>(TP(0), TP(4), cF);
    return ngm;
#undef TP
}

__global__ void __launch_bounds__(512, 2)
passB(const int* __restrict__ lengths) {
    extern __shared__ __nv_bfloat16 dyn[];
    __nv_bfloat16* tiles = dyn;
    float* red = (float*)(dyn + 8 * TILE);
    const int cc = blockIdx.x, b = blockIdx.y;
    const int L = lengths[b];
    const int totalChunks = (L + 7) >> 3;
    const int nch = min(totalChunks - cc * 8, 8);
    if (nch <= 0) return;
    const int cb = cc * 8;
    const int idx = threadIdx.x * 8;
    const size_t mat = (size_t)S * S;

    if (nch == 1) {
        *(uint4*)(g_buf2 + ((size_t)cc * BB + b) * mat + idx) =
            *(const uint4*)(g_buf1 + ((size_t)cb * BB + b) * mat + idx);
        if (threadIdx.x == 0) g_off2[cc * BB + b] = g_off1[cb * BB + b];
        return;
    }

    float offsum = 0.f;
    for (int k = 0; k < nch; ++k) {
        smem_put(*(const uint4*)(g_buf1 + ((size_t)(cb + k) * BB + b) * mat + idx),
                 tiles + k * TILE);
        offsum += g_off1[(cb + k) * BB + b];
    }
    __syncthreads();

    float cF[2][4];
    int ngm = tree_combine(tiles, nch, cF);

    float scale, sft;
    exact_scale16(cF, red, scale, sft);
    wb_global16(cF, scale, g_buf2 + ((size_t)cc * BB + b) * mat);
    if (threadIdx.x == 0)
        g_off2[cc * BB + b] = offsum + 4.f * (float)ngm + sft;
}

__global__ void __launch_bounds__(512, 1)
passC(const int* __restrict__ lengths, float* __restrict__ out) {
    extern __shared__ __nv_bfloat16 dyn[];
    __nv_bfloat16* tiles = dyn;
    float* red = (float*)(dyn + 8 * TILE);
    const int b = blockIdx.x;
    const int L = lengths[b];
    const int totalChunks = (L + 7) >> 3;
    const int n = (totalChunks + 7) >> 3;
    const int idx = threadIdx.x * 8;
    const int w = threadIdx.x >> 5, lane = threadIdx.x & 31;
    const size_t mat = (size_t)S * S;

    float s, off;
    if (n == 1) {
        uint4 v = *(const uint4*)(g_buf2 + (size_t)b * mat + idx);
        const __nv_bfloat16* h = (const __nv_bfloat16*)&v;
        s = 0.f;
#pragma unroll
        for (int q = 0; q < 8; ++q) s += __bfloat162float(h[q]);
        off = g_off2[b];
    } else {
        float offsum = 0.f;
        for (int k = 0; k < n; ++k) {
            smem_put(*(const uint4*)(g_buf2 + ((size_t)k * BB + b) * mat + idx),
                     tiles + k * TILE);
            offsum += g_off2[k * BB + b];
        }
        __syncthreads();
        float cF[2][4];
        int ngm = tree_combine(tiles, n, cF);
        off = offsum + 4.f * (float)ngm;
        s = 0.f;
#pragma unroll
        for (int nt = 0; nt < 2; ++nt)
#pragma unroll
            for (int q = 0; q < 4; ++q) s += cF[nt][q];
    }

#pragma unroll
    for (int o = 16; o; o >>= 1) s += __shfl_xor_sync(0xffffffffu, s, o);
    if (lane == 0) red[w] = s;
    __syncthreads();
    if (threadIdx.x == 0) {
        float tot = red[0];
#pragma unroll
        for (int i = 1; i < 16; ++i) tot += red[i];
        double vt = ((double)log2f(tot) + (double)off) * 0.6931471805599453094;
        out[b] = (float)vt;
    }
}

extern "C" void kernel_launch(void* const* d_in, const int* in_sizes, int n_in,
                              void* d_out, int out_size)
{
    const float* theta   = (const float*)d_in[0];
    const int*   lengths = (const int*)d_in[1];
    float*       out     = (float*)d_out;

    const int DYN = 8 * TILE * (int)sizeof(__nv_bfloat16) + 32 * (int)sizeof(float);
    static int configured = -1;
    if (configured < 0) {
        cudaFuncSetAttribute(passB, cudaFuncAttributeMaxDynamicSharedMemorySize, DYN);
        cudaFuncSetAttribute(passC, cudaFuncAttributeMaxDynamicSharedMemorySize, DYN);
        configured = 1;
    }

    passA<<<dim3(TT / 8, BB), 128>>>(theta, lengths);
    passB<<<dim3(TT / 64, BB), 512, DYN>>>(lengths);
    passC<<<BB, 512, DYN>>>(lengths, out);
}

// round 14
// speedup vs baseline: 1.0882x; 1.0003x over previous
#include <cuda_runtime.h>
#include <cuda_bf16.h>
#include <cstdint>

// PackedViterbi as a parallel matrix-product tree.
// R13 passA: REGISTER-RESIDENT running product. Each of 4 warps owns a 16x64
// C slab (c[8][4]). Key identity: mma m16n8k16's C-fragment layout == A-fragment
// layout under n->k renaming, so the next GEMM's A operand is packed from the
// previous C registers (32 FMUL + 16 CVT) -- A never round-trips through SMEM.
// Per-GEMM SMEM traffic drops 76KB -> 40KB (the measured crossbar wall).
// 128-thread CTAs, 3 rotating leaf buffers, conv(leaf j+2) overlapped with GEMM j,
// 6 CTAs/SM. passB/passC = R10's proven 512-thread binary-tree combine.

static constexpr int S   = 64;
static constexpr int TT  = 512;
static constexpr int BB  = 64;
static constexpr int LDA = 72;            // padded SMEM stride (bf16 elems)
static constexpr int TILE = S * LDA;      // bf16 elems per smem tile

__device__ __nv_bfloat16 g_buf1[64 * BB * S * S];
__device__ float         g_off1[64 * BB];
__device__ __nv_bfloat16 g_buf2[8 * BB * S * S];
__device__ float         g_off2[8 * BB];

__device__ __forceinline__ float ex2f_(float x) {
    float y; asm("ex2.approx.ftz.f32 %0, %1;" : "=f"(y) : "f"(x)); return y;
}
__device__ __forceinline__ void mma16816(float c[4], const uint32_t a[4],
                                         uint32_t b0, uint32_t b1) {
    asm volatile(
        "mma.sync.aligned.m16n8k16.row.col.f32.bf16.bf16.f32 "
        "{%0,%1,%2,%3}, {%4,%5,%6,%7}, {%8,%9}, {%0,%1,%2,%3};\n"
        : "+f"(c[0]), "+f"(c[1]), "+f"(c[2]), "+f"(c[3])
        : "r"(a[0]), "r"(a[1]), "r"(a[2]), "r"(a[3]), "r"(b0), "r"(b1));
}
__device__ __forceinline__ void ldm_x4_t(uint32_t a[4], uint32_t addr) {
    asm volatile("ldmatrix.sync.aligned.m8n8.x4.trans.shared.b16 {%0,%1,%2,%3}, [%4];"
                 : "=r"(a[0]), "=r"(a[1]), "=r"(a[2]), "=r"(a[3]) : "r"(addr));
}
__device__ __forceinline__ void ldm_x2_t(uint32_t b[2], uint32_t addr) {
    asm volatile("ldmatrix.sync.aligned.m8n8.x2.trans.shared.b16 {%0,%1}, [%2];"
                 : "=r"(b[0]), "=r"(b[1]) : "r"(addr));
}
__device__ __forceinline__ uint32_t bf2u(__nv_bfloat162 v) {
    return *reinterpret_cast<uint32_t*>(&v);
}

// ===================== passA helpers (128 threads, 4 warps) ====================

// convert one 64x64 theta leaf -> E' = 2^(x*log2e - 16) into smem (row-major).
// thread covers row r = tid>>1, cols (tid&1)*32 .. +31.
__device__ __forceinline__ void conv_store128(const float* __restrict__ g,
                                              __nv_bfloat16* s) {
    const float L2E = 1.4426950408889634f;
    const int r  = threadIdx.x >> 1;
    const int c0 = (threadIdx.x & 1) * 32;
    const float* src = g + r * S + c0;
    __nv_bfloat16* dst = s + r * LDA + c0;
#pragma unroll
    for (int h = 0; h < 4; ++h) {
        float4 v0 = *(const float4*)(src + h * 8);
        float4 v1 = *(const float4*)(src + h * 8 + 4);
        __nv_bfloat16 t[8];
        t[0] = __float2bfloat16(ex2f_(fmaf(v0.x, L2E, -16.f)));
        t[1] = __float2bfloat16(ex2f_(fmaf(v0.y, L2E, -16.f)));
        t[2] = __float2bfloat16(ex2f_(fmaf(v0.z, L2E, -16.f)));
        t[3] = __float2bfloat16(ex2f_(fmaf(v0.w, L2E, -16.f)));
        t[4] = __float2bfloat16(ex2f_(fmaf(v1.x, L2E, -16.f)));
        t[5] = __float2bfloat16(ex2f_(fmaf(v1.y, L2E, -16.f)));
        t[6] = __float2bfloat16(ex2f_(fmaf(v1.z, L2E, -16.f)));
        t[7] = __float2bfloat16(ex2f_(fmaf(v1.w, L2E, -16.f)));
        *(uint4*)(dst + h * 8) = *(uint4*)t;
    }
}

// c[8][4] += apack(16x64 A slab) * B(64x64 from smem), C zeroed inside.
__device__ __forceinline__ void mma_chain(const uint32_t apack[16],
                                          const __nv_bfloat16* Bsm,
                                          float c[8][4]) {
    const int lane = threadIdx.x & 31;
    const int g = lane >> 2, t4 = lane & 3;
#pragma unroll
    for (int nt = 0; nt < 8; ++nt) {
        c[nt][0] = c[nt][1] = c[nt][2] = c[nt][3] = 0.f;
        const __nv_bfloat16* bb = Bsm + (nt * 8 + g) * LDA + t4 * 2;
#pragma unroll
        for (int ks = 0; ks < 4; ++ks) {
            uint32_t b0 = *(const uint32_t*)(bb + ks * 16);
            uint32_t b1 = *(const uint32_t*)(bb + ks * 16 + 8);
            mma16816(c[nt], apack + ks * 4, b0, b1);
        }
    }
}

// A-fragments for the NEXT GEMM from current C regs (scaled): layout identity.
__device__ __forceinline__ void packA(const float c[8][4], uint32_t apack[16],
                                      float scl) {
#pragma unroll
    for (int ks = 0; ks < 4; ++ks) {
        apack[ks*4+0] = bf2u(__floats2bfloat162_rn(c[2*ks][0]*scl,   c[2*ks][1]*scl));
        apack[ks*4+1] = bf2u(__floats2bfloat162_rn(c[2*ks][2]*scl,   c[2*ks][3]*scl));
        apack[ks*4+2] = bf2u(__floats2bfloat162_rn(c[2*ks+1][0]*scl, c[2*ks+1][1]*scl));
        apack[ks*4+3] = bf2u(__floats2bfloat162_rn(c[2*ks+1][2]*scl, c[2*ks+1][3]*scl));
    }
}

// exact power-of-2 scale over 4 warps
__device__ __forceinline__ void exact_scale4(const float c[8][4], float* red,
                                             float& scale, float& sft) {
    const int tid = threadIdx.x;
    const int w = tid >> 5, lane = tid & 31;
    float m = 0.f;
#pragma unroll
    for (int nt = 0; nt < 8; ++nt)
#pragma unroll
        for (int q = 0; q < 4; ++q) m = fmaxf(m, c[nt][q]);
#pragma unroll
    for (int o = 16; o; o >>= 1)
        m = fmaxf(m, __shfl_xor_sync(0xffffffffu, m, o));
    if (lane == 0) red[w] = m;
    __syncthreads();
    if (tid == 0) {
        float mm = fmaxf(fmaxf(red[0], red[1]), fmaxf(red[2], red[3]));
        int s = (int)((__float_as_uint(mm) >> 23) & 0xFF) - 126;
        red[4] = __uint_as_float((uint32_t)(127 - s) << 23);
        red[5] = (float)s;
    }
    __syncthreads();
    scale = red[4];
    sft   = red[5];
}

__device__ __forceinline__ void wb_global4(const float c[8][4], float scl,
                                           __nv_bfloat16* __restrict__ dst) {
    const int tid = threadIdx.x;
    const int w = tid >> 5, lane = tid & 31;
    const int g = lane >> 2, t4 = lane & 3;
    const int rb = w * 16;
#pragma unroll
    for (int nt = 0; nt < 8; ++nt) {
        int col = nt * 8 + t4 * 2;
        __nv_bfloat162 lo = __floats2bfloat162_rn(c[nt][0] * scl, c[nt][1] * scl);
        __nv_bfloat162 hi = __floats2bfloat162_rn(c[nt][2] * scl, c[nt][3] * scl);
        *(uint32_t*)(dst + (rb + g) * S + col)     = bf2u(lo);
        *(uint32_t*)(dst + (rb + g + 8) * S + col) = bf2u(hi);
    }
}

// ---- Pass A -------------------------------------------------------------------
__global__ void __launch_bounds__(128, 6)
passA(const float* __restrict__ theta, const int* __restrict__ lengths) {
    __shared__ __nv_bfloat16 B3[3][TILE];
    __shared__ float red[8];
    const int c = blockIdx.x, b = blockIdx.y;
    const int L = lengths[b];
    const int t0 = c * 8;
    if (L <= t0) return;
    const int thi = min(L, t0 + 8);
    const int ngemm = thi - t0 - 1;
    const size_t mat = (size_t)S * S;
    const float* base = theta + (size_t)b * mat;
    const size_t tstride = (size_t)BB * mat;

    conv_store128(base + (size_t)t0 * tstride, B3[0]);
    if (ngemm > 0) conv_store128(base + (size_t)(t0 + 1) * tstride, B3[1]);
    __syncthreads();

    if (ngemm == 0) {                      // single leaf: store E^T
        const int r = threadIdx.x >> 1, c0 = (threadIdx.x & 1) * 32;
        __nv_bfloat16* dst = g_buf1 + ((size_t)c * BB + b) * mat + r * S + c0;
#pragma unroll
        for (int h = 0; h < 4; ++h) {
            __nv_bfloat16 t[8];
#pragma unroll
            for (int q = 0; q < 8; ++q) t[q] = B3[0][(c0 + h * 8 + q) * LDA + r];
            *(uint4*)(dst + h * 8) = *(uint4*)t;
        }
        if (threadIdx.x == 0) g_off1[c * BB + b] = 16.f;
        return;
    }

    const int w = threadIdx.x >> 5, lane = threadIdx.x & 31;
    const int rb = w * 16;

    uint32_t apack[16];
    {   // A = E_{t0}^T via ldmatrix.trans on the direct tile
        const int mi = lane >> 3, r8 = lane & 7;
        const int colA = rb + ((mi & 1) ? 8 : 0);
        const int rowO = ((mi & 2) ? 8 : 0) + r8;
#pragma unroll
        for (int ks = 0; ks < 4; ++ks) {
            uint32_t ad = (uint32_t)__cvta_generic_to_shared(
                B3[0] + (ks * 16 + rowO) * LDA + colA);
            ldm_x4_t(apack + ks * 4, ad);
        }
    }
    if (ngemm > 1) conv_store128(base + (size_t)(t0 + 2) * tstride, B3[2]);

    float c_[8][4];
    mma_chain(apack, B3[1], c_);           // GEMM 0
    __syncthreads();

    for (int j = 1; j < ngemm; ++j) {
        packA(c_, apack, 512.f);           // fixed x2^9, from registers
        if (j + 1 < ngemm)
            conv_store128(base + (size_t)(t0 + j + 2) * tstride, B3[(j + 2) % 3]);
        mma_chain(apack, B3[(j + 1) % 3], c_);
        __syncthreads();
    }

    float scale, sft;
    exact_scale4(c_, red, scale, sft);
    wb_global4(c_, scale, g_buf1 + ((size_t)c * BB + b) * mat);
    if (threadIdx.x == 0)
        g_off1[c * BB + b] = 16.f * (float)(thi - t0) - 9.f * (float)(ngemm - 1) + sft;
}

// ===================== passB / passC (R10, 512 threads) ========================

__device__ __forceinline__ void smem_put(const uint4& v, __nv_bfloat16* s) {
    int idx = threadIdx.x * 8;
    *(uint4*)(s + (idx >> 6) * LDA + (idx & 63)) = v;
}

template <bool BLDM>
__device__ __forceinline__ void cta_compute16(const __nv_bfloat16* Asm,
                                              const __nv_bfloat16* Btsm,
                                              float c[2][4]) {
    const int tid = threadIdx.x;
    const int w = tid >> 5, lane = tid & 31;
    const int g = lane >> 2, t4 = lane & 3;
    const int rb = (w >> 2) * 16;
    const int ng = (w & 3) * 2;

    uint32_t a[4][4];
#pragma unroll
    for (int ks = 0; ks < 4; ++ks) {
        const __nv_bfloat16* baseA = Asm + (rb + g) * LDA + ks * 16 + t4 * 2;
        a[ks][0] = *(const uint32_t*)(baseA);
        a[ks][1] = *(const uint32_t*)(baseA + 8 * LDA);
        a[ks][2] = *(const uint32_t*)(baseA + 8);
        a[ks][3] = *(const uint32_t*)(baseA + 8 * LDA + 8);
    }
#pragma unroll
    for (int nt = 0; nt < 2; ++nt) {
        c[nt][0] = c[nt][1] = c[nt][2] = c[nt][3] = 0.f;
        const int n0 = (ng + nt) * 8;
#pragma unroll
        for (int ks = 0; ks < 4; ++ks) {
            uint32_t b0, b1;
            if (BLDM) {
                const int r8 = lane & 7, ti = (lane >> 3) & 1;
                uint32_t ad = (uint32_t)__cvta_generic_to_shared(
                    Btsm + (ks * 16 + ti * 8 + r8) * LDA + n0);
                uint32_t bb[2]; ldm_x2_t(bb, ad);
                b0 = bb[0]; b1 = bb[1];
            } else {
                const __nv_bfloat16* bb = Btsm + (n0 + g) * LDA + ks * 16 + t4 * 2;
                b0 = *(const uint32_t*)bb;
                b1 = *(const uint32_t*)(bb + 8);
            }
            mma16816(c[nt], a[ks], b0, b1);
        }
    }
}

__device__ __forceinline__ void wb_smem16(const float c[2][4], float scl,
                                          __nv_bfloat16* dst) {
    const int tid = threadIdx.x;
    const int w = tid >> 5, lane = tid & 31;
    const int g = lane >> 2, t4 = lane & 3;
    const int rb = (w >> 2) * 16;
    const int ng = (w & 3) * 2;
#pragma unroll
    for (int nt = 0; nt < 2; ++nt) {
        int col = (ng + nt) * 8 + t4 * 2;
        __nv_bfloat162 lo = __floats2bfloat162_rn(c[nt][0] * scl, c[nt][1] * scl);
        __nv_bfloat162 hi = __floats2bfloat162_rn(c[nt][2] * scl, c[nt][3] * scl);
        *(uint32_t*)(dst + (rb + g) * LDA + col)     = bf2u(lo);
        *(uint32_t*)(dst + (rb + g + 8) * LDA + col) = bf2u(hi);
    }
}
__device__ __forceinline__ void wb_global16(const float c[2][4], float scl,
                                            __nv_bfloat16* __restrict__ dst) {
    const int tid = threadIdx.x;
    const int w = tid >> 5, lane = tid & 31;
    const int g = lane >> 2, t4 = lane & 3;
    const int rb = (w >> 2) * 16;
    const int ng = (w & 3) * 2;
#pragma unroll
    for (int nt = 0; nt < 2; ++nt) {
        int col = (ng + nt) * 8 + t4 * 2;
        __nv_bfloat162 lo = __floats2bfloat162_rn(c[nt][0] * scl, c[nt][1] * scl);
        __nv_bfloat162 hi = __floats2bfloat162_rn(c[nt][2] * scl, c[nt][3] * scl);
        *(uint32_t*)(dst + (rb + g) * S + col)     = bf2u(lo);
        *(uint32_t*)(dst + (rb + g + 8) * S + col) = bf2u(hi);
    }
}
__device__ __forceinline__ void exact_scale16(const float c[2][4], float* red,
                                              float& scale, float& sft) {
    const int tid = threadIdx.x;
    const int w = tid >> 5, lane = tid & 31;
    float m = 0.f;
#pragma unroll
    for (int nt = 0; nt < 2; ++nt)
#pragma unroll
        for (int q = 0; q < 4; ++q) m = fmaxf(m, c[nt][q]);
#pragma unroll
    for (int o = 16; o; o >>= 1)
        m = fmaxf(m, __shfl_xor_sync(0xffffffffu, m, o));
    if (lane == 0) red[w] = m;
    __syncthreads();
    if (tid == 0) {
        float mm = red[0];
#pragma unroll
        for (int i = 1; i < 16; ++i) mm = fmaxf(mm, red[i]);
        int s = (int)((__float_as_uint(mm) >> 23) & 0xFF) - 126;
        red[16] = __uint_as_float((uint32_t)(127 - s) << 23);
        red[17] = (float)s;
    }
    __syncthreads();
    scale = red[16];
    sft   = red[17];
}

__device__ __forceinline__ int tree_combine(__nv_bfloat16* tiles, int n,
                                            float cF[2][4]) {
    int ngm = 0;
    float c1[2][4];
    const float FS = 0.0625f;
#define TP(i) (tiles + (i) * TILE)
    cta_compute16<true>(TP(0), TP(1), cF);
    if (n == 2) return 0;
    if (n > 3) cta_compute16<true>(TP(2), TP(3), c1);
    __syncthreads();
    wb_smem16(cF, FS, TP(0)); ++ngm;
    if (n > 3) { wb_smem16(c1, FS, TP(2)); ++ngm; }
    __syncthreads();
    if (n > 5) {
        cta_compute16<true>(TP(4), TP(5), cF);
        if (n > 7) cta_compute16<true>(TP(6), TP(7), c1);
        __syncthreads();
        wb_smem16(cF, FS, TP(4)); ++ngm;
        if (n > 7) { wb_smem16(c1, FS, TP(6)); ++ngm; }
        __syncthreads();
    }
    if (n <= 4) {
        cta_compute16<true>(TP(0), TP(2), cF);
        return ngm;
    }
    cta_compute16<true>(TP(0), TP(2), cF);
    if (n > 6) cta_compute16<true>(TP(4), TP(6), c1);
    __syncthreads();
    wb_smem16(cF, FS, TP(0)); ++ngm;
    if (n > 6) { wb_smem16(c1, FS, TP(4)); ++ngm; }
    __syncthreads();
    cta_compute16<true>(TP(0), TP(4), cF);
    return ngm;
#undef TP
}

__global__ void __launch_bounds__(512, 2)
passB(const int* __restrict__ lengths) {
    extern __shared__ __nv_bfloat16 dyn[];
    __nv_bfloat16* tiles = dyn;
    float* red = (float*)(dyn + 8 * TILE);
    const int cc = blockIdx.x, b = blockIdx.y;
    const int L = lengths[b];
    const int totalChunks = (L + 7) >> 3;
    const int nch = min(totalChunks - cc * 8, 8);
    if (nch <= 0) return;
    const int cb = cc * 8;
    const int idx = threadIdx.x * 8;
    const size_t mat = (size_t)S * S;

    if (nch == 1) {
        *(uint4*)(g_buf2 + ((size_t)cc * BB + b) * mat + idx) =
            *(const uint4*)(g_buf1 + ((size_t)cb * BB + b) * mat + idx);
        if (threadIdx.x == 0) g_off2[cc * BB + b] = g_off1[cb * BB + b];
        return;
    }

    float offsum = 0.f;
    for (int k = 0; k < nch; ++k) {
        smem_put(*(const uint4*)(g_buf1 + ((size_t)(cb + k) * BB + b) * mat + idx),
                 tiles + k * TILE);
        offsum += g_off1[(cb + k) * BB + b];
    }
    __syncthreads();

    float cF[2][4];
    int ngm = tree_combine(tiles, nch, cF);

    float scale, sft;
    exact_scale16(cF, red, scale, sft);
    wb_global16(cF, scale, g_buf2 + ((size_t)cc * BB + b) * mat);
    if (threadIdx.x == 0)
        g_off2[cc * BB + b] = offsum + 4.f * (float)ngm + sft;
}

__global__ void __launch_bounds__(512, 1)
passC(const int* __restrict__ lengths, float* __restrict__ out) {
    extern __shared__ __nv_bfloat16 dyn[];
    __nv_bfloat16* tiles = dyn;
    float* red = (float*)(dyn + 8 * TILE);
    const int b = blockIdx.x;
    const int L = lengths[b];
    const int totalChunks = (L + 7) >> 3;
    const int n = (totalChunks + 7) >> 3;
    const int idx = threadIdx.x * 8;
    const int w = threadIdx.x >> 5, lane = threadIdx.x & 31;
    const size_t mat = (size_t)S * S;

    float s, off;
    if (n == 1) {
        uint4 v = *(const uint4*)(g_buf2 + (size_t)b * mat + idx);
        const __nv_bfloat16* h = (const __nv_bfloat16*)&v;
        s = 0.f;
#pragma unroll
        for (int q = 0; q < 8; ++q) s += __bfloat162float(h[q]);
        off = g_off2[b];
    } else {
        float offsum = 0.f;
        for (int k = 0; k < n; ++k) {
            smem_put(*(const uint4*)(g_buf2 + ((size_t)k * BB + b) * mat + idx),
                     tiles + k * TILE);
            offsum += g_off2[k * BB + b];
        }
        __syncthreads();
        float cF[2][4];
        int ngm = tree_combine(tiles, n, cF);
        off = offsum + 4.f * (float)ngm;
        s = 0.f;
#pragma unroll
        for (int nt = 0; nt < 2; ++nt)
#pragma unroll
            for (int q = 0; q < 4; ++q) s += cF[nt][q];
    }

#pragma unroll
    for (int o = 16; o; o >>= 1) s += __shfl_xor_sync(0xffffffffu, s, o);
    if (lane == 0) red[w] = s;
    __syncthreads();
    if (threadIdx.x == 0) {
        float tot = red[0];
#pragma unroll
        for (int i = 1; i < 16; ++i) tot += red[i];
        double vt = ((double)log2f(tot) + (double)off) * 0.6931471805599453094;
        out[b] = (float)vt;
    }
}

extern "C" void kernel_launch(void* const* d_in, const int* in_sizes, int n_in,
                              void* d_out, int out_size)
{
    const float* theta   = (const float*)d_in[0];
    const int*   lengths = (const int*)d_in[1];
    float*       out     = (float*)d_out;

    const int DYN = 8 * TILE * (int)sizeof(__nv_bfloat16) + 32 * (int)sizeof(float);
    static int configured = -1;
    if (configured < 0) {
        cudaFuncSetAttribute(passB, cudaFuncAttributeMaxDynamicSharedMemorySize, DYN);
        cudaFuncSetAttribute(passC, cudaFuncAttributeMaxDynamicSharedMemorySize, DYN);
        configured = 1;
    }

    passA<<<dim3(TT / 8, BB), 128>>>(theta, lengths);
    passB<<<dim3(TT / 64, BB), 512, DYN>>>(lengths);
    passC<<<BB, 512, DYN>>>(lengths, out);
}

// round 16
// speedup vs baseline: 1.3957x; 1.2826x over previous
#include <cuda_runtime.h>
#include <cuda_bf16.h>
#include <cstdint>

// PackedViterbi as a parallel matrix-product tree (transpose-free, fixed
// power-of-2 per-GEMM scaling, ping-pong tiles, 1 barrier/GEMM).
// R16: chunk size 8 -> 16 in passA. Total GEMM count is invariant across the
// tree, but passA executes GEMMs ~4.5x cheaper than passB/C, so shifting work
// into passA (0.875 -> 0.9375 GEMMs/leaf) while HALVING passB/C work + chunk
// prologue count is net positive. All component code = R10 (measured fastest).

static constexpr int S   = 64;
static constexpr int TT  = 512;
static constexpr int BB  = 64;
static constexpr int CH  = 16;            // leaves per passA chunk
static constexpr int NC  = TT / CH;       // 32 chunks per sequence
static constexpr int LDA = 72;
static constexpr int TILE = S * LDA;

__device__ __nv_bfloat16 g_buf1[NC * BB * S * S];
__device__ float         g_off1[NC * BB];
__device__ __nv_bfloat16 g_buf2[4 * BB * S * S];
__device__ float         g_off2[4 * BB];

__device__ __forceinline__ float ex2f_(float x) {
    float y; asm("ex2.approx.ftz.f32 %0, %1;" : "=f"(y) : "f"(x)); return y;
}
__device__ __forceinline__ uint32_t bf2u(__nv_bfloat162 v) { return *reinterpret_cast<uint32_t*>(&v); }
__device__ __forceinline__ void mma16816(float c[4], const uint32_t a[4],
                                         uint32_t b0, uint32_t b1) {
    asm volatile(
        "mma.sync.aligned.m16n8k16.row.col.f32.bf16.bf16.f32 "
        "{%0,%1,%2,%3}, {%4,%5,%6,%7}, {%8,%9}, {%0,%1,%2,%3};\n"
        : "+f"(c[0]), "+f"(c[1]), "+f"(c[2]), "+f"(c[3])
        : "r"(a[0]), "r"(a[1]), "r"(a[2]), "r"(a[3]), "r"(b0), "r"(b1));
}
__device__ __forceinline__ void ldm_x4_t(uint32_t a[4], uint32_t addr) {
    asm volatile("ldmatrix.sync.aligned.m8n8.x4.trans.shared.b16 {%0,%1,%2,%3}, [%4];"
                 : "=r"(a[0]), "=r"(a[1]), "=r"(a[2]), "=r"(a[3]) : "r"(addr));
}
__device__ __forceinline__ void ldm_x2_t(uint32_t b[2], uint32_t addr) {
    asm volatile("ldmatrix.sync.aligned.m8n8.x2.trans.shared.b16 {%0,%1}, [%2];"
                 : "=r"(b[0]), "=r"(b[1]) : "r"(addr));
}

struct F8 { float4 a, b; };
__device__ __forceinline__ F8 ldg8(const float* __restrict__ p) {
    F8 r; const float4* q = (const float4*)p; r.a = q[0]; r.b = q[1]; return r;
}
__device__ __forceinline__ void conv_store(const F8& v, __nv_bfloat16* s) {
    const float L2E = 1.4426950408889634f;
    int idx = threadIdx.x * 8;
    float e[8];
    e[0] = ex2f_(fmaf(v.a.x, L2E, -16.f)); e[1] = ex2f_(fmaf(v.a.y, L2E, -16.f));
    e[2] = ex2f_(fmaf(v.a.z, L2E, -16.f)); e[3] = ex2f_(fmaf(v.a.w, L2E, -16.f));
    e[4] = ex2f_(fmaf(v.b.x, L2E, -16.f)); e[5] = ex2f_(fmaf(v.b.y, L2E, -16.f));
    e[6] = ex2f_(fmaf(v.b.z, L2E, -16.f)); e[7] = ex2f_(fmaf(v.b.w, L2E, -16.f));
    __nv_bfloat16 t[8];
#pragma unroll
    for (int q = 0; q < 8; ++q) t[q] = __float2bfloat16(e[q]);
    *(uint4*)(s + (idx >> 6) * LDA + (idx & 63)) = *(uint4*)t;
}
__device__ __forceinline__ void smem_put(const uint4& v, __nv_bfloat16* s) {
    int idx = threadIdx.x * 8;
    *(uint4*)(s + (idx >> 6) * LDA + (idx & 63)) = v;
}

template <bool ATRANS, bool BLDM>
__device__ __forceinline__ void cta_compute(const __nv_bfloat16* Asm,
                                            const __nv_bfloat16* Btsm,
                                            float c[2][4]) {
    const int tid = threadIdx.x;
    const int w = tid >> 5, lane = tid & 31;
    const int g = lane >> 2, t4 = lane & 3;
    const int rb = (w >> 2) * 16;
    const int ng = (w & 3) * 2;

    uint32_t a[4][4];
    if (ATRANS) {
        const int mi = lane >> 3, r8 = lane & 7;
        const int colA = rb + ((mi & 1) ? 8 : 0);
        const int rowO = ((mi & 2) ? 8 : 0) + r8;
#pragma unroll
        for (int ks = 0; ks < 4; ++ks) {
            uint32_t ad = (uint32_t)__cvta_generic_to_shared(
                Asm + (ks * 16 + rowO) * LDA + colA);
            ldm_x4_t(a[ks], ad);
        }
    } else {
#pragma unroll
        for (int ks = 0; ks < 4; ++ks) {
            const __nv_bfloat16* base = Asm + (rb + g) * LDA + ks * 16 + t4 * 2;
            a[ks][0] = *(const uint32_t*)(base);
            a[ks][1] = *(const uint32_t*)(base + 8 * LDA);
            a[ks][2] = *(const uint32_t*)(base + 8);
            a[ks][3] = *(const uint32_t*)(base + 8 * LDA + 8);
        }
    }
#pragma unroll
    for (int nt = 0; nt < 2; ++nt) {
        c[nt][0] = c[nt][1] = c[nt][2] = c[nt][3] = 0.f;
        const int n0 = (ng + nt) * 8;
#pragma unroll
        for (int ks = 0; ks < 4; ++ks) {
            uint32_t b0, b1;
            if (BLDM) {
                const int r8 = lane & 7, ti = (lane >> 3) & 1;
                uint32_t ad = (uint32_t)__cvta_generic_to_shared(
                    Btsm + (ks * 16 + ti * 8 + r8) * LDA + n0);
                uint32_t bb[2]; ldm_x2_t(bb, ad);
                b0 = bb[0]; b1 = bb[1];
            } else {
                const __nv_bfloat16* bb = Btsm + (n0 + g) * LDA + ks * 16 + t4 * 2;
                b0 = *(const uint32_t*)bb;
                b1 = *(const uint32_t*)(bb + 8);
            }
            mma16816(c[nt], a[ks], b0, b1);
        }
    }
}

__device__ __forceinline__ void wb_smem(const float c[2][4], float scl,
                                        __nv_bfloat16* dst) {
    const int tid = threadIdx.x;
    const int w = tid >> 5, lane = tid & 31;
    const int g = lane >> 2, t4 = lane & 3;
    const int rb = (w >> 2) * 16;
    const int ng = (w & 3) * 2;
#pragma unroll
    for (int nt = 0; nt < 2; ++nt) {
        int col = (ng + nt) * 8 + t4 * 2;
        *(uint32_t*)(dst + (rb + g) * LDA + col)     = bf2u(__floats2bfloat162_rn(c[nt][0] * scl, c[nt][1] * scl));
        *(uint32_t*)(dst + (rb + g + 8) * LDA + col) = bf2u(__floats2bfloat162_rn(c[nt][2] * scl, c[nt][3] * scl));
    }
}
__device__ __forceinline__ void wb_global(const float c[2][4], float scl,
                                          __nv_bfloat16* __restrict__ dst) {
    const int tid = threadIdx.x;
    const int w = tid >> 5, lane = tid & 31;
    const int g = lane >> 2, t4 = lane & 3;
    const int rb = (w >> 2) * 16;
    const int ng = (w & 3) * 2;
#pragma unroll
    for (int nt = 0; nt < 2; ++nt) {
        int col = (ng + nt) * 8 + t4 * 2;
        *(uint32_t*)(dst + (rb + g) * S + col)     = bf2u(__floats2bfloat162_rn(c[nt][0] * scl, c[nt][1] * scl));
        *(uint32_t*)(dst + (rb + g + 8) * S + col) = bf2u(__floats2bfloat162_rn(c[nt][2] * scl, c[nt][3] * scl));
    }
}

__device__ __forceinline__ void exact_scale(const float c[2][4], float* red,
                                            float& scale, float& sft) {
    const int tid = threadIdx.x;
    const int w = tid >> 5, lane = tid & 31;
    float m = 0.f;
#pragma unroll
    for (int nt = 0; nt < 2; ++nt)
#pragma unroll
        for (int q = 0; q < 4; ++q) m = fmaxf(m, c[nt][q]);
#pragma unroll
    for (int o = 16; o; o >>= 1)
        m = fmaxf(m, __shfl_xor_sync(0xffffffffu, m, o));
    if (lane == 0) red[w] = m;
    __syncthreads();
    if (tid == 0) {
        float mm = red[0];
#pragma unroll
        for (int i = 1; i < 16; ++i) mm = fmaxf(mm, red[i]);
        int s = (int)((__float_as_uint(mm) >> 23) & 0xFF) - 126;
        red[16] = __uint_as_float((uint32_t)(127 - s) << 23);
        red[17] = (float)s;
    }
    __syncthreads();
    scale = red[16];
    sft   = red[17];
}

// ---- Pass A (R10 body, chunk = 16 leaves) -------------------------------------
__global__ void __launch_bounds__(512, 2)
passA(const float* __restrict__ theta, const int* __restrict__ lengths) {
    __shared__ __nv_bfloat16 Abuf[2][TILE];
    __shared__ __nv_bfloat16 Bbuf[2][TILE];
    __shared__ float red[20];
    const int c = blockIdx.x, b = blockIdx.y;
    const int L = lengths[b];
    const int t0 = c * CH;
    if (L <= t0) return;
    const int thi = min(L, t0 + CH);
    const int idx = threadIdx.x * 8;
    const size_t mat = (size_t)S * S;
    const float* tbase = theta + (size_t)b * mat + idx;
    const size_t tstride = (size_t)BB * mat;

    F8 rA = ldg8(tbase + (size_t)t0 * tstride);

    if (thi == t0 + 1) {                   // single leaf: M = E^T
        conv_store(rA, Abuf[0]);
        __syncthreads();
        const int r = idx >> 6, c0 = idx & 63;
        __nv_bfloat16 t[8];
#pragma unroll
        for (int q = 0; q < 8; ++q) t[q] = Abuf[0][(c0 + q) * LDA + r];
        *(uint4*)(g_buf1 + ((size_t)c * BB + b) * mat + idx) = *(uint4*)t;
        if (threadIdx.x == 0) g_off1[c * BB + b] = 16.f;
        return;
    }

    F8 rN = ldg8(tbase + (size_t)(t0 + 1) * tstride);
    conv_store(rA, Abuf[0]);
    conv_store(rN, Bbuf[0]);
    if (t0 + 2 < thi) rN = ldg8(tbase + (size_t)(t0 + 2) * tstride);
    __syncthreads();

    float c_[2][4];
    cta_compute<true, false>(Abuf[0], Bbuf[0], c_);   // GEMM 0 (A = E^T)

    const int ngemm = thi - t0 - 1;
    int pa = 0, pb = 0;
    for (int k = 1; k < ngemm; ++k) {
        conv_store(rN, Bbuf[pb ^ 1]);
        if (t0 + k + 2 < thi) rN = ldg8(tbase + (size_t)(t0 + k + 2) * tstride);
        wb_smem(c_, 512.f, Abuf[pa ^ 1]);             // fixed x2^9
        pa ^= 1; pb ^= 1;
        __syncthreads();
        cta_compute<false, false>(Abuf[pa], Bbuf[pb], c_);
    }

    float scale, sft;
    exact_scale(c_, red, scale, sft);
    wb_global(c_, scale, g_buf1 + ((size_t)c * BB + b) * mat);
    if (threadIdx.x == 0)
        g_off1[c * BB + b] = 16.f * (float)(thi - t0) - 9.f * (float)(ngemm - 1) + sft;
}

// ---- binary-tree combine of n (2..8) tiles in smem, ascending order ----------
__device__ __forceinline__ int tree_combine(__nv_bfloat16* tiles, int n,
                                            float cF[2][4]) {
    int ngm = 0;
    float c1[2][4];
    const float FS = 0.0625f;
#define TP(i) (tiles + (i) * TILE)
    cta_compute<false, true>(TP(0), TP(1), cF);
    if (n == 2) return 0;
    if (n > 3) cta_compute<false, true>(TP(2), TP(3), c1);
    __syncthreads();
    wb_smem(cF, FS, TP(0)); ++ngm;
    if (n > 3) { wb_smem(c1, FS, TP(2)); ++ngm; }
    __syncthreads();
    if (n > 5) {
        cta_compute<false, true>(TP(4), TP(5), cF);
        if (n > 7) cta_compute<false, true>(TP(6), TP(7), c1);
        __syncthreads();
        wb_smem(cF, FS, TP(4)); ++ngm;
        if (n > 7) { wb_smem(c1, FS, TP(6)); ++ngm; }
        __syncthreads();
    }
    if (n <= 4) {
        cta_compute<false, true>(TP(0), TP(2), cF);
        return ngm;
    }
    cta_compute<false, true>(TP(0), TP(2), cF);
    if (n > 6) cta_compute<false, true>(TP(4), TP(6), c1);
    __syncthreads();
    wb_smem(cF, FS, TP(0)); ++ngm;
    if (n > 6) { wb_smem(c1, FS, TP(4)); ++ngm; }
    __syncthreads();
    cta_compute<false, true>(TP(0), TP(4), cF);
    return ngm;
#undef TP
}

// ---- Pass B: combine 8 chunks of 16 leaves ------------------------------------
__global__ void __launch_bounds__(512, 2)
passB(const int* __restrict__ lengths) {
    extern __shared__ __nv_bfloat16 dyn[];
    __nv_bfloat16* tiles = dyn;
    float* red = (float*)(dyn + 8 * TILE);
    const int cc = blockIdx.x, b = blockIdx.y;
    const int L = lengths[b];
    const int totalChunks = (L + CH - 1) / CH;
    const int nch = min(totalChunks - cc * 8, 8);
    if (nch <= 0) return;
    const int cb = cc * 8;
    const int idx = threadIdx.x * 8;
    const size_t mat = (size_t)S * S;

    if (nch == 1) {
        *(uint4*)(g_buf2 + ((size_t)cc * BB + b) * mat + idx) =
            *(const uint4*)(g_buf1 + ((size_t)cb * BB + b) * mat + idx);
        if (threadIdx.x == 0) g_off2[cc * BB + b] = g_off1[cb * BB + b];
        return;
    }

    float offsum = 0.f;
    for (int k = 0; k < nch; ++k) {
        smem_put(*(const uint4*)(g_buf1 + ((size_t)(cb + k) * BB + b) * mat + idx),
                 tiles + k * TILE);
        offsum += g_off1[(cb + k) * BB + b];
    }
    __syncthreads();

    float cF[2][4];
    int ngm = tree_combine(tiles, nch, cF);

    float scale, sft;
    exact_scale(cF, red, scale, sft);
    wb_global(cF, scale, g_buf2 + ((size_t)cc * BB + b) * mat);
    if (threadIdx.x == 0)
        g_off2[cc * BB + b] = offsum + 4.f * (float)ngm + sft;
}

// ---- Pass C: combine up to 4 super-chunks --------------------------------------
__global__ void __launch_bounds__(512, 1)
passC(const int* __restrict__ lengths, float* __restrict__ out) {
    extern __shared__ __nv_bfloat16 dyn[];
    __nv_bfloat16* tiles = dyn;
    float* red = (float*)(dyn + 8 * TILE);
    const int b = blockIdx.x;
    const int L = lengths[b];
    const int totalChunks = (L + CH - 1) / CH;
    const int n = (totalChunks + 7) >> 3;         // <= 4
    const int idx = threadIdx.x * 8;
    const int w = threadIdx.x >> 5, lane = threadIdx.x & 31;
    const size_t mat = (size_t)S * S;

    float s, off;
    if (n == 1) {
        uint4 v = *(const uint4*)(g_buf2 + (size_t)b * mat + idx);
        const __nv_bfloat16* h = (const __nv_bfloat16*)&v;
        s = 0.f;
#pragma unroll
        for (int q = 0; q < 8; ++q) s += __bfloat162float(h[q]);
        off = g_off2[b];
    } else {
        float offsum = 0.f;
        for (int k = 0; k < n; ++k) {
            smem_put(*(const uint4*)(g_buf2 + ((size_t)k * BB + b) * mat + idx),
                     tiles + k * TILE);
            offsum += g_off2[k * BB + b];
        }
        __syncthreads();
        float cF[2][4];
        int ngm = tree_combine(tiles, n, cF);
        off = offsum + 4.f * (float)ngm;
        s = 0.f;
#pragma unroll
        for (int nt = 0; nt < 2; ++nt)
#pragma unroll
            for (int q = 0; q < 4; ++q) s += cF[nt][q];
    }

#pragma unroll
    for (int o = 16; o; o >>= 1) s += __shfl_xor_sync(0xffffffffu, s, o);
    if (lane == 0) red[w] = s;
    __syncthreads();
    if (threadIdx.x == 0) {
        float tot = red[0];
#pragma unroll
        for (int i = 1; i < 16; ++i) tot += red[i];
        out[b] = (float)(((double)log2f(tot) + (double)off) * 0.6931471805599453094);
    }
}

extern "C" void kernel_launch(void* const* d_in, const int* in_sizes, int n_in,
                              void* d_out, int out_size)
{
    const float* theta   = (const float*)d_in[0];
    const int*   lengths = (const int*)d_in[1];
    float*       out     = (float*)d_out;

    const int DYN = 8 * TILE * (int)sizeof(__nv_bfloat16) + 32 * (int)sizeof(float);
    static int configured = -1;
    if (configured < 0) {
        cudaFuncSetAttribute(passB, cudaFuncAttributeMaxDynamicSharedMemorySize, DYN);
        cudaFuncSetAttribute(passC, cudaFuncAttributeMaxDynamicSharedMemorySize, DYN);
        configured = 1;
    }

    passA<<<dim3(NC, BB), 512>>>(theta, lengths);
    passB<<<dim3(NC / 8, BB), 512, DYN>>>(lengths);
    passC<<<BB, 512, DYN>>>(lengths, out);
}